// round 13
// baseline (speedup 1.0000x reference)
#include <cuda_runtime.h>
#include <cuda_fp16.h>
#include <cstdint>

#define Bb 4
#define Nn 10000
#define Ee 160000
#define Mm 4
#define Hh 64
#define OUTd 64
#define Ff 64

#define ROWS (Bb*Nn*Mm)      /* 160000 projected rows, each 128 -> 64 */
#define EDGES (Bb*Ee)        /* 640000 */
#define NODES (Bb*Nn)        /* 40000 target buckets */

// Scratch (allocation-free rule: __device__ globals)
__device__ __half             g_nh[(size_t)ROWS * OUTd];  // 20.5 MB projected (fp16)
__device__ int                g_count[NODES];             // histogram by (b,tgt)
__device__ int                g_beg[NODES];               // segment start
__device__ int                g_pos[NODES];               // fill cursors
__device__ unsigned long long g_rec[EDGES];               // packed {src, coeff}
__device__ int                g_cursor;                   // allocator cursor

// ---------------------------------------------------------------------------
// Side stream + fork/join events (created at load; not device allocations)
// ---------------------------------------------------------------------------
static cudaStream_t s_side;
static cudaEvent_t  ev_fork, ev_join;
static struct SideInit {
    SideInit() {
        cudaStreamCreateWithFlags(&s_side, cudaStreamNonBlocking);
        cudaEventCreateWithFlags(&ev_fork, cudaEventDisableTiming);
        cudaEventCreateWithFlags(&ev_join, cudaEventDisableTiming);
    }
} s_side_init;

// ---------------------------------------------------------------------------
// Kernel 0: zero histogram + allocator cursor
// ---------------------------------------------------------------------------
__global__ void k_zero()
{
    int i = blockIdx.x * blockDim.x + threadIdx.x;
    if (i < NODES) g_count[i] = 0;
    if (i == 0) g_cursor = 0;
}

// ---------------------------------------------------------------------------
// Kernel 1: target histogram (only needs idx)
// ---------------------------------------------------------------------------
__global__ __launch_bounds__(256)
void k_hist(const int* __restrict__ idx)
{
    int e = blockIdx.x * blockDim.x + threadIdx.x;
    if (e >= EDGES) return;
    int b   = e / Ee;
    int tgt = idx[(size_t)e * 2 + 1];
    atomicAdd(&g_count[b * Nn + tgt], 1);
}

// ---------------------------------------------------------------------------
// Kernel 2: warp-aggregated segment allocation
// ---------------------------------------------------------------------------
__global__ __launch_bounds__(256)
void k_alloc()
{
    int n    = blockIdx.x * blockDim.x + threadIdx.x;
    int lane = threadIdx.x & 31;

    int c = (n < NODES) ? g_count[n] : 0;

    int s = c;
    #pragma unroll
    for (int off = 1; off < 32; off <<= 1) {
        int v = __shfl_up_sync(0xFFFFFFFFu, s, off);
        if (lane >= off) s += v;
    }
    int total = __shfl_sync(0xFFFFFFFFu, s, 31);

    int base = 0;
    if (lane == 31) base = atomicAdd(&g_cursor, total);
    base = __shfl_sync(0xFFFFFFFFu, base, 31);

    if (n < NODES) {
        int beg = base + s - c;
        g_beg[n] = beg;
        g_pos[n] = beg;
    }
}

// ---------------------------------------------------------------------------
// Kernel 3: projection (side stream). 8 rows x 4 cols per thread,
// 128-row tile, 256 threads, 2 CTA/SM. Epilogue converts to fp16.
// ---------------------------------------------------------------------------
#define PROJ_ROWS_PER_BLK 128
#define PROJ_BLOCKS (ROWS / PROJ_ROWS_PER_BLK)   /* 1250 */
#define XPITCH 132
#define PROJ_SMEM_BYTES ((128*64 + PROJ_ROWS_PER_BLK*XPITCH) * 4)  /* 100352 */

__global__ __launch_bounds__(256, 2)
void k_project(const float* __restrict__ node,
               const float* __restrict__ hidden,
               const float* __restrict__ Wnh,
               const float* __restrict__ bnh)
{
    extern __shared__ float sm[];
    float* Ws = sm;                  // [128][64]
    float* Xs = sm + 128 * 64;       // [128][XPITCH]

    const int tid  = threadIdx.x;
    const int row0 = blockIdx.x * PROJ_ROWS_PER_BLK;

    #pragma unroll
    for (int i = tid; i < 128 * 64; i += 256) Ws[i] = Wnh[i];

    // X tile: 128 rows x 32 float4 (16 node + 16 hidden per row), coalesced
    const float4* node4   = (const float4*)node;
    const float4* hidden4 = (const float4*)hidden;
    #pragma unroll
    for (int i = tid; i < PROJ_ROWS_PER_BLK * 32; i += 256) {
        int r = i >> 5;
        int q = i & 31;
        int grow = row0 + r;
        float4 v;
        int col;
        if (q < 16) { v = __ldg(&node4[(size_t)grow * 16 + q]);          col = q * 4; }
        else        { v = __ldg(&hidden4[(size_t)grow * 16 + (q - 16)]); col = 64 + (q - 16) * 4; }
        *(float4*)&Xs[r * XPITCH + col] = v;
    }
    __syncthreads();

    const int obase = (tid & 15) * 4;   // 16 col-groups * 4 = 64 outputs
    const int rbase = (tid >> 4) * 8;   // 16 row-groups * 8 = 128 rows

    float4 acc[8];
    {
        float4 b = *(const float4*)&bnh[obase];
        #pragma unroll
        for (int r = 0; r < 8; r++) acc[r] = b;
    }

    #pragma unroll 2
    for (int cb = 0; cb < 128; cb += 4) {
        const float4 w0 = *(const float4*)&Ws[(cb + 0) * 64 + obase];
        const float4 w1 = *(const float4*)&Ws[(cb + 1) * 64 + obase];
        const float4 w2 = *(const float4*)&Ws[(cb + 2) * 64 + obase];
        const float4 w3 = *(const float4*)&Ws[(cb + 3) * 64 + obase];
        #pragma unroll
        for (int r = 0; r < 8; r++) {
            const float4 x = *(const float4*)&Xs[(rbase + r) * XPITCH + cb];
            acc[r].x += x.x * w0.x; acc[r].y += x.x * w0.y; acc[r].z += x.x * w0.z; acc[r].w += x.x * w0.w;
            acc[r].x += x.y * w1.x; acc[r].y += x.y * w1.y; acc[r].z += x.y * w1.z; acc[r].w += x.y * w1.w;
            acc[r].x += x.z * w2.x; acc[r].y += x.z * w2.y; acc[r].z += x.z * w2.z; acc[r].w += x.z * w2.w;
            acc[r].x += x.w * w3.x; acc[r].y += x.w * w3.y; acc[r].z += x.w * w3.z; acc[r].w += x.w * w3.w;
        }
    }

    #pragma unroll
    for (int r = 0; r < 8; r++) {
        size_t off = (size_t)(row0 + rbase + r) * 64 + obase;   // half units
        __half2 h0 = __floats2half2_rn(acc[r].x, acc[r].y);
        __half2 h1 = __floats2half2_rn(acc[r].z, acc[r].w);
        uint2 pk;
        pk.x = *(unsigned*)&h0;
        pk.y = *(unsigned*)&h1;
        *(uint2*)(g_nh + off) = pk;    // 8-byte aligned (obase % 4 == 0)
    }
}

// ---------------------------------------------------------------------------
// Kernel 4: per-edge gate + CSR fill. FOUR edges per warp for MLP.
// ---------------------------------------------------------------------------
__global__ __launch_bounds__(256)
void k_coeff_fill(const float* __restrict__ ef,
                  const float* __restrict__ We,
                  const float* __restrict__ be,
                  const int*   __restrict__ idx)
{
    int wq   = (blockIdx.x * blockDim.x + threadIdx.x) >> 5;   // warp id
    int lane = threadIdx.x & 31;
    int e0   = wq * 4;
    if (e0 >= EDGES) return;

    float wlo = __ldg(&We[lane]);
    float whi = __ldg(&We[lane + 32]);

    float s0, s1, s2, s3;
    {
        const float* r0 = ef + (size_t)(e0 + 0) * 64;
        const float* r1 = ef + (size_t)(e0 + 1) * 64;
        const float* r2 = ef + (size_t)(e0 + 2) * 64;
        const float* r3 = ef + (size_t)(e0 + 3) * 64;
        float a0 = __ldg(r0 + lane), b0 = __ldg(r0 + lane + 32);
        float a1 = __ldg(r1 + lane), b1 = __ldg(r1 + lane + 32);
        float a2 = __ldg(r2 + lane), b2 = __ldg(r2 + lane + 32);
        float a3 = __ldg(r3 + lane), b3 = __ldg(r3 + lane + 32);
        s0 = a0 * wlo + b0 * whi;
        s1 = a1 * wlo + b1 * whi;
        s2 = a2 * wlo + b2 * whi;
        s3 = a3 * wlo + b3 * whi;
    }

    #pragma unroll
    for (int off = 16; off > 0; off >>= 1) {
        s0 += __shfl_xor_sync(0xFFFFFFFFu, s0, off);
        s1 += __shfl_xor_sync(0xFFFFFFFFu, s1, off);
        s2 += __shfl_xor_sync(0xFFFFFFFFu, s2, off);
        s3 += __shfl_xor_sync(0xFFFFFFFFu, s3, off);
    }

    if (lane < 4) {
        int e = e0 + lane;
        float s = (lane == 0) ? s0 : (lane == 1) ? s1 : (lane == 2) ? s2 : s3;
        float cf = s + __ldg(&be[0]);
        int2 st  = __ldg((const int2*)idx + e);      // {src, tgt}
        int  b   = e / Ee;
        int  p   = atomicAdd(&g_pos[b * Nn + st.y], 1);
        unsigned long long rec =
            (unsigned long long)(unsigned)st.x |
            ((unsigned long long)__float_as_uint(cf) << 32);
        g_rec[p] = rec;
    }
}

// ---------------------------------------------------------------------------
// Kernel 5: accumulate (fp16 gather). One warp per node. Per edge a single
// LDG.128 gathers 8 halves/lane (512 B/warp); fp32 accumulation; streaming
// record loads / output stores keep g_nh hot in L2.
// ---------------------------------------------------------------------------
__global__ __launch_bounds__(256)
void k_accum(float* __restrict__ out)
{
    int n    = (blockIdx.x * blockDim.x + threadIdx.x) >> 5;
    int lane = threadIdx.x & 31;
    if (n >= NODES) return;

    int beg = g_beg[n];
    int cnt = g_count[n];
    int b   = n / Nn;

    const __half* basep = g_nh + (size_t)b * Nn * 256;

    float a[8];
    #pragma unroll
    for (int i = 0; i < 8; i++) a[i] = 0.f;

    for (int c0 = 0; c0 < cnt; c0 += 32) {
        int m = cnt - c0; if (m > 32) m = 32;
        unsigned long long rec = 0;
        if (lane < m) rec = __ldcs(&g_rec[beg + c0 + lane]);   // streaming
        int   rsrc = (int)(unsigned)(rec & 0xFFFFFFFFull);
        float rcf  = __uint_as_float((unsigned)(rec >> 32));

        #pragma unroll 8
        for (int k = 0; k < m; k++) {
            int   sidx = __shfl_sync(0xFFFFFFFFu, rsrc, k);
            float cf   = __shfl_sync(0xFFFFFFFFu, rcf,  k);
            const float4* p = (const float4*)(basep + (size_t)sidx * 256);
            float4 raw = __ldg(p + lane);                      // 8 halves
            const __half2* h2 = (const __half2*)&raw;
            float2 f;
            f = __half22float2(h2[0]); a[0] += cf * f.x; a[1] += cf * f.y;
            f = __half22float2(h2[1]); a[2] += cf * f.x; a[3] += cf * f.y;
            f = __half22float2(h2[2]); a[4] += cf * f.x; a[5] += cf * f.y;
            f = __half22float2(h2[3]); a[6] += cf * f.x; a[7] += cf * f.y;
        }
    }

    float* t = out + (size_t)n * 256 + lane * 8;
    __stcs((float4*)t,     make_float4(a[0], a[1], a[2], a[3]));
    __stcs((float4*)t + 1, make_float4(a[4], a[5], a[6], a[7]));
}

// ---------------------------------------------------------------------------
// launch graph (edge chain enqueued FIRST so its blocks win SM slots):
//   stream0: zero -> hist -> alloc -> coeff_fill ┐
//   side:    project (dep: graph entry only)     ├-> accum (stream0)
// inputs: node_fts, hidden, edge_fts, W_nh, b_nh, W_e, b_e, edge_indices(i32)
// ---------------------------------------------------------------------------
extern "C" void kernel_launch(void* const* d_in, const int* in_sizes, int n_in,
                              void* d_out, int out_size)
{
    const float* node   = (const float*)d_in[0];
    const float* hidden = (const float*)d_in[1];
    const float* ef     = (const float*)d_in[2];
    const float* Wnh    = (const float*)d_in[3];
    const float* bnh    = (const float*)d_in[4];
    const float* We     = (const float*)d_in[5];
    const float* be     = (const float*)d_in[6];
    const int*   idx    = (const int*)d_in[7];
    float*       out    = (float*)d_out;

    cudaFuncSetAttribute(k_project, cudaFuncAttributeMaxDynamicSharedMemorySize,
                         PROJ_SMEM_BYTES);

    // fork point at graph entry
    cudaEventRecord(ev_fork, 0);
    cudaStreamWaitEvent(s_side, ev_fork, 0);

    // edge chain on the capture stream (enqueued first)
    k_zero<<<(NODES + 255) / 256, 256>>>();
    k_hist<<<(EDGES + 255) / 256, 256>>>(idx);
    k_alloc<<<(NODES + 255) / 256, 256>>>();
    k_coeff_fill<<<(EDGES / 4 + 7) / 8, 256>>>(ef, We, be, idx);

    // projection on side stream (independent branch)
    k_project<<<PROJ_BLOCKS, 256, PROJ_SMEM_BYTES, s_side>>>(node, hidden, Wnh, bnh);
    cudaEventRecord(ev_join, s_side);

    // join: accum needs both g_nh (project) and the CSR records (edge chain)
    cudaStreamWaitEvent(0, ev_join, 0);
    k_accum<<<(NODES * 32 + 255) / 256, 256>>>(out);
}